// round 1
// baseline (speedup 1.0000x reference)
#include <cuda_runtime.h>
#include <cstdint>

#define K  11
#define TT 512
#define BB 4096
#define IMPOSSIBLE_F (-10000.0f)

// Precomputed constant tables (written by setup kernel each launch; deterministic).
__device__ float g_transM[K * K];   // masked transitions (log domain, for score)
__device__ float g_expT[K * K];     // exp(masked transitions) (for alpha recursion)
__device__ float g_startM[K];       // masked start transitions
__device__ float g_endM[K];         // end transitions (no constraint)
__device__ int   g_u8mode;          // 1 if mask buffer is 1-byte bool, 0 if 4-byte

__global__ void zero_out_kernel(float* out) {
    if (threadIdx.x == 0) out[0] = 0.0f;
}

__global__ void setup_kernel(const float* __restrict__ trans,
                             const float* __restrict__ startv,
                             const float* __restrict__ endv,
                             const void*  __restrict__ maskp) {
    int t = threadIdx.x;
    if (t < K * K) {
        int i = t / K, j = t % K;
        // BIO constraints: into O (j==0) always allowed; into B (j odd) always
        // allowed; into I_i (j even >=2) only from B_i (i==j-1) or I_i (i==j).
        bool allowed = (j == 0) || (j & 1) || (i == j - 1) || (i == j);
        float v = allowed ? trans[t] : IMPOSSIBLE_F;
        g_transM[t] = v;
        g_expT[t]   = expf(v);   // exp(-10000) underflows to exactly 0 -> forbidden
    }
    if (t < K) {
        bool sforb = (t >= 2) && ((t & 1) == 0);   // cannot start with I_i
        g_startM[t] = sforb ? IMPOSSIBLE_F : startv[t];
        g_endM[t]   = endv[t];
    }
    if (t == 0) {
        // Lengths >= T/2 = 256, so mask[0][1] is true. If the buffer is 1-byte
        // bool, byte[1] == 1. If it is int32 (01 00 00 00 ...) or float32
        // (00 00 80 3F ...), byte[1] == 0.
        const unsigned char* mb = (const unsigned char*)maskp;
        g_u8mode = (mb[1] != 0) ? 1 : 0;
    }
}

// One 16-lane group per batch row. Lane j (j < 11) owns tag-state j.
// Alpha recursion kept as ratios r_j = exp(alpha_j - alpha_0) with scalar
// log-accumulator A0 = alpha_0, renormalized every step by the O state.
__global__ void __launch_bounds__(256)
crf_kernel(const float* __restrict__ em,
           const void*  __restrict__ maskp,
           const int*   __restrict__ tags,
           float* __restrict__ out) {
    __shared__ float sh_trans[K * K];
    if (threadIdx.x < K * K) sh_trans[threadIdx.x] = g_transM[threadIdx.x];
    __syncthreads();

    const int lane = threadIdx.x & 15;
    const int grp  = threadIdx.x >> 4;
    const int b    = blockIdx.x * 16 + grp;
    // Mask of my 16-lane half-warp (two groups per warp can diverge on loop
    // trip count, so never sync across the full warp inside the loop).
    const unsigned hmask = ((threadIdx.x & 31) < 16) ? 0x0000FFFFu : 0xFFFF0000u;
    const bool act = (lane < K);

    // Per-lane column of expT: eT[i] = exp(trans[i][lane])
    float eT[K];
#pragma unroll
    for (int i = 0; i < K; i++) eT[i] = act ? g_expT[i * K + lane] : 0.0f;
    float start_l = act ? g_startM[lane] : -1e30f;
    float end_l   = act ? g_endM[lane]   : 0.0f;
    float expE    = act ? __expf(end_l)  : 0.0f;

    // Sequence length = popcount of prefix mask row.
    int len = 0;
    if (g_u8mode) {
        const unsigned char* m = (const unsigned char*)maskp + (size_t)b * TT;
#pragma unroll 8
        for (int t = lane; t < TT; t += 16) len += (m[t] != 0);
    } else {
        const unsigned* m = (const unsigned*)maskp + (size_t)b * TT;
#pragma unroll 8
        for (int t = lane; t < TT; t += 16) len += (m[t] != 0);
    }
#pragma unroll
    for (int k = 8; k; k >>= 1) len += __shfl_xor_sync(hmask, len, k, 16);

    const float* erow = em   + (size_t)b * TT * K;
    const int*   trow = tags + (size_t)b * TT;

    // t = 0
    float emv = act ? erow[lane] : 0.0f;
    float a_l = start_l + emv;                      // alpha_0[lane]
    float a_0 = __shfl_sync(hmask, a_l, 0, 16);     // alpha_0[O]
    float r   = act ? __expf(a_l - a_0) : 0.0f;     // ratio vs O state
    float A0  = a_0;                                // running alpha[O]
    int ptag  = trow[0];
    float score = __shfl_sync(hmask, start_l, ptag, 16)
                + __shfl_sync(hmask, emv,     ptag, 16);

    // Prefetch t = 1 (len >= 256 guaranteed)
    float em_nx = act ? erow[K + lane] : 0.0f;
    int   tg_nx = trow[1];

    for (int t = 1; t < len; t++) {
        float emc = em_nx;
        int   tg  = tg_nx;
        int   tn  = (t + 1 < TT) ? (t + 1) : t;     // clamp: value unused past len
        em_nx = act ? erow[(size_t)tn * K + lane] : 0.0f;
        tg_nx = trow[tn];

        float e0 = __shfl_sync(hmask, emc, 0, 16);
        float pe = __expf(emc - e0);                // off critical path (prefetched em)

        // s_j = sum_i r_i * expT[i][j]  (broadcast r_i to all lanes)
        float s1 = 0.0f, s2 = 0.0f;
#pragma unroll
        for (int i = 0; i < K; i++) {
            float ri = __shfl_sync(hmask, r, i, 16);
            if (i & 1) s2 = fmaf(ri, eT[i], s2);
            else       s1 = fmaf(ri, eT[i], s1);
        }
        float s  = s1 + s2;
        float s0 = __shfl_sync(hmask, s, 0, 16);
        float inv = __frcp_rn(s0);
        r = act ? (s * inv) * pe : 0.0f;            // new ratios
        A0 += e0 + __logf(s0);                      // side chain, not on recurrence

        // Gold path score (exact log-domain, includes IMPOSSIBLE terms)
        float emt = __shfl_sync(hmask, emc, tg, 16);
        score += sh_trans[ptag * K + tg] + emt;
        ptag = tg;
    }

    // z = A0 + log( sum_j r_j * exp(end_j) )
    float v = r * expE;
#pragma unroll
    for (int k = 8; k; k >>= 1) v += __shfl_xor_sync(hmask, v, k, 16);
    float z = A0 + __logf(v);

    score += __shfl_sync(hmask, end_l, ptag, 16);   // end[last_tag]

    if (lane == 0) atomicAdd(out, (score - z) * (1.0f / (float)BB));
}

extern "C" void kernel_launch(void* const* d_in, const int* in_sizes, int n_in,
                              void* d_out, int out_size) {
    const float* em     = (const float*)d_in[0];
    const void*  maskp  = d_in[1];
    const int*   tags   = (const int*)d_in[2];
    const float* trans  = (const float*)d_in[3];
    const float* startv = (const float*)d_in[4];
    const float* endv   = (const float*)d_in[5];
    float* out = (float*)d_out;

    zero_out_kernel<<<1, 32>>>(out);
    setup_kernel<<<1, 128>>>(trans, startv, endv, maskp);
    crf_kernel<<<BB / 16, 256>>>(em, maskp, tags, out);
}

// round 2
// speedup vs baseline: 2.4028x; 2.4028x over previous
#include <cuda_runtime.h>
#include <cstdint>

#define K  11
#define TT 512
#define BB 4096
#define IMPOSSIBLE_F (-10000.0f)

// Precomputed constant tables (written by setup kernel each launch; deterministic).
__device__ float g_transM[K * K];   // masked transitions (log domain, for score)
__device__ float g_expT[K * K];     // exp(masked transitions) (for alpha recursion)
__device__ float g_startM[K];       // masked start transitions
__device__ float g_endM[K];         // end transitions (no constraint)
__device__ int   g_u8mode;          // 1 if mask buffer is 1-byte bool, 0 if 4-byte

__global__ void setup_kernel(const float* __restrict__ trans,
                             const float* __restrict__ startv,
                             const float* __restrict__ endv,
                             const void*  __restrict__ maskp,
                             float* __restrict__ out) {
    int t = threadIdx.x;
    if (t < K * K) {
        int i = t / K, j = t % K;
        // BIO constraints: into O (j==0) always allowed; into B (j odd) always
        // allowed; into I_i (j even >=2) only from B_i (i==j-1) or I_i (i==j).
        bool allowed = (j == 0) || (j & 1) || (i == j - 1) || (i == j);
        float v = allowed ? trans[t] : IMPOSSIBLE_F;
        g_transM[t] = v;
        g_expT[t]   = expf(v);   // exp(-10000) underflows to exactly 0 -> forbidden
    }
    if (t < K) {
        bool sforb = (t >= 2) && ((t & 1) == 0);   // cannot start with I_i
        g_startM[t] = sforb ? IMPOSSIBLE_F : startv[t];
        g_endM[t]   = endv[t];
    }
    if (t == 0) {
        // Lengths >= T/2 = 256, so mask[0][1] is true. If the buffer is 1-byte
        // bool, byte[1] == 1. If it is int32/float32, byte[1] == 0.
        const unsigned char* mb = (const unsigned char*)maskp;
        g_u8mode = (mb[1] != 0) ? 1 : 0;
        out[0] = 0.0f;
    }
}

// One 16-lane group per batch row. Lane j (j < 11) owns tag-state j.
// Unnormalized exp-domain state rho_j; renormalized by rho[0] every 8 steps
// (lazy renorm): growth per step <= ~12*e^5.5 ~ 3000 -> 3000^8 ~ 6.5e27 < fp32 max.
// A0 accumulates only the chunk renorm logs; z = A0 + log(sum rho_j e^{end_j}).
__global__ void __launch_bounds__(256)
crf_kernel(const float* __restrict__ em,
           const void*  __restrict__ maskp,
           const int*   __restrict__ tags,
           float* __restrict__ out) {
    __shared__ float sh_trans[K * K];
    if (threadIdx.x < K * K) sh_trans[threadIdx.x] = g_transM[threadIdx.x];
    __syncthreads();

    const int lane = threadIdx.x & 15;
    const int grp  = threadIdx.x >> 4;
    const int b    = blockIdx.x * 16 + grp;
    const unsigned hmask = ((threadIdx.x & 31) < 16) ? 0x0000FFFFu : 0xFFFF0000u;
    const bool act = (lane < K);
    const int laneK = act ? lane : 0;   // clamped column for safe loads

    // Per-lane column of expT: eT[i] = exp(trans[i][lane]); 0 for inactive lanes
    // so inactive rho stays exactly 0 through the recursion.
    float eT[K];
#pragma unroll
    for (int i = 0; i < K; i++) eT[i] = act ? g_expT[i * K + lane] : 0.0f;
    float start_l = act ? g_startM[lane] : -1e30f;
    float end_l   = act ? g_endM[lane]   : 0.0f;
    float expE    = act ? __expf(end_l)  : 0.0f;

    // Sequence length = popcount of prefix mask row.
    int len = 0;
    if (g_u8mode) {
        const unsigned char* m = (const unsigned char*)maskp + (size_t)b * TT;
#pragma unroll 8
        for (int t = lane; t < TT; t += 16) len += (m[t] != 0);
    } else {
        const unsigned* m = (const unsigned*)maskp + (size_t)b * TT;
#pragma unroll 8
        for (int t = lane; t < TT; t += 16) len += (m[t] != 0);
    }
#pragma unroll
    for (int k = 8; k; k >>= 1) len += __shfl_xor_sync(hmask, len, k, 16);

    const float* erow = em   + (size_t)b * TT * K;
    const int*   trow = tags + (size_t)b * TT;

    // t = 0 (normalized start)
    float emv = erow[laneK];
    float a_l = start_l + emv;
    float a_0 = __shfl_sync(hmask, a_l, 0, 16);
    float rho = act ? __expf(a_l - a_0) : 0.0f;
    float A0  = a_0;
    int ptag  = trow[0];
    float score = __shfl_sync(hmask, start_l, ptag, 16)
                + __shfl_sync(hmask, emv,     ptag, 16);

    // Double-buffered 8-step register queues (deep prefetch: ~16 LDG in flight,
    // issued a full chunk (~800 cyc of compute) before first use).
    float emA[8], emB[8];
    int   tgA[8], tgB[8];

#define LOAD_CHUNK(EMQ, TGQ, TB)                                          \
    {                                                                     \
        _Pragma("unroll")                                                 \
        for (int k_ = 0; k_ < 8; k_++) {                                  \
            int tt_ = (TB) + k_;                                          \
            tt_ = (tt_ < TT) ? tt_ : (TT - 1);  /* clamped; unused past len */ \
            EMQ[k_] = erow[(size_t)tt_ * K + laneK];                      \
            TGQ[k_] = trow[tt_];                                          \
        }                                                                 \
    }

#define STEP_BODY(EMC, TG)                                                \
    {                                                                     \
        float emc_ = (EMC);                                               \
        int   tg_  = (TG);                                                \
        float pe_  = __expf(emc_);     /* off the recurrence chain */     \
        float s1_ = 0.0f, s2_ = 0.0f;                                     \
        _Pragma("unroll")                                                 \
        for (int i_ = 0; i_ < K; i_++) {                                  \
            float ri_ = __shfl_sync(hmask, rho, i_, 16);                  \
            if (i_ & 1) s2_ = fmaf(ri_, eT[i_], s2_);                     \
            else        s1_ = fmaf(ri_, eT[i_], s1_);                     \
        }                                                                 \
        rho = (s1_ + s2_) * pe_;                                          \
        float emt_ = __shfl_sync(hmask, emc_, tg_, 16);                   \
        score += sh_trans[ptag * K + tg_] + emt_;                         \
        ptag = tg_;                                                       \
    }

#define CHUNK_BODY(EMQ, TGQ)                                              \
    {                                                                     \
        _Pragma("unroll")                                                 \
        for (int k_c = 0; k_c < 8; k_c++) STEP_BODY(EMQ[k_c], TGQ[k_c])   \
        float m_ = __shfl_sync(hmask, rho, 0, 16);                        \
        rho *= __frcp_rn(m_);                                             \
        A0  += __logf(m_);                                                \
    }

    int t = 1;
    LOAD_CHUNK(emA, tgA, t);
    bool useA = true;
    while (t + 8 <= len) {
        if (useA) { LOAD_CHUNK(emB, tgB, t + 8); CHUNK_BODY(emA, tgA); }
        else      { LOAD_CHUNK(emA, tgA, t + 8); CHUNK_BODY(emB, tgB); }
        useA = !useA;
        t += 8;
    }
    // Remainder (< 8 steps): direct loads; one-time latency, negligible.
    for (; t < len; t++) {
        float emc = erow[(size_t)t * K + laneK];
        int   tg  = trow[t];
        STEP_BODY(emc, tg)
    }

    // z = A0 + log( sum_j rho_j * exp(end_j) )   (rho growth since last renorm
    // bounded by <=7 unrenormalized steps -> safe in fp32)
    float v = rho * expE;
#pragma unroll
    for (int k = 8; k; k >>= 1) v += __shfl_xor_sync(hmask, v, k, 16);
    float z = A0 + __logf(v);

    score += __shfl_sync(hmask, end_l, ptag, 16);   // end[last_tag]

    if (lane == 0) atomicAdd(out, (score - z) * (1.0f / (float)BB));
}

extern "C" void kernel_launch(void* const* d_in, const int* in_sizes, int n_in,
                              void* d_out, int out_size) {
    const float* em     = (const float*)d_in[0];
    const void*  maskp  = d_in[1];
    const int*   tags   = (const int*)d_in[2];
    const float* trans  = (const float*)d_in[3];
    const float* startv = (const float*)d_in[4];
    const float* endv   = (const float*)d_in[5];
    float* out = (float*)d_out;

    setup_kernel<<<1, 128>>>(trans, startv, endv, maskp, out);
    crf_kernel<<<BB / 16, 256>>>(em, maskp, tags, out);
}